// round 1
// baseline (speedup 1.0000x reference)
#include <cuda_runtime.h>

#define NN 50000
#define NP 50048            // padded to multiple of 64 (gemm tile)
#define NE 600000
#define NG 64
#define HID 128
#define NL 4
#define INDIM 5
#define NCLS 5
#define SCAN_NB 49          // ceil(50000/1024)
#define GEMM_SMEM ((128*128 + 64*132)*4)

// ---------------- device scratch (static globals; no allocation) ----------------
__device__ int   d_deg[NN];
__device__ int   d_rowptr[NN + 1];
__device__ int   d_cursor[NN];
__device__ int   d_col[NE];
__device__ float d_w[NE];
__device__ float d_dinv[NN];
__device__ int   d_bsum[64];
__device__ float d_bufH[(size_t)NP * HID];   // h0 = x@Wp+bp
__device__ float d_bufM[(size_t)NP * HID];   // m  = h@Wg
__device__ float d_bufA[(size_t)NP * HID];   // agg (pre-BN)
__device__ float d_sums[2 * HID];
__device__ float d_bnA[HID];
__device__ float d_bnB[HID];
__device__ int   d_gstart[NG + 1];
__device__ float d_pooled[NG * 2 * HID];
__device__ float d_h1[NG * HID];
__device__ float d_h2[NG * (HID / 2)];

// ---------------- f32x2 packed-fp32 helpers (sm_103a) ----------------
__device__ __forceinline__ unsigned long long pack2(float x, float y) {
    unsigned long long r;
    asm("mov.b64 %0, {%1, %2};" : "=l"(r) : "f"(x), "f"(y));
    return r;
}
__device__ __forceinline__ void fma2(unsigned long long &d, unsigned long long a, unsigned long long b) {
    asm("fma.rn.f32x2 %0, %1, %2, %0;" : "+l"(d) : "l"(a), "l"(b));
}
__device__ __forceinline__ float2 unpack2(unsigned long long v) {
    float2 r;
    asm("mov.b64 {%0, %1}, %2;" : "=f"(r.x), "=f"(r.y) : "l"(v));
    return r;
}

// ---------------- CSR build ----------------
__global__ void zero_deg_k() {
    int i = blockIdx.x * blockDim.x + threadIdx.x;
    if (i < NN) d_deg[i] = 0;
}

__global__ void hist_k(const int* __restrict__ ei) {
    int e = blockIdx.x * blockDim.x + threadIdx.x;
    if (e < NE) atomicAdd(&d_deg[ei[NE + e]], 1);
}

__global__ void scan1_k() {
    __shared__ int sh[1024];
    int tid = threadIdx.x;
    int i = blockIdx.x * 1024 + tid;
    int v = (i < NN) ? d_deg[i] : 0;
    sh[tid] = v;
    __syncthreads();
    for (int off = 1; off < 1024; off <<= 1) {
        int t = (tid >= off) ? sh[tid - off] : 0;
        __syncthreads();
        sh[tid] += t;
        __syncthreads();
    }
    if (i < NN) d_rowptr[i] = sh[tid] - v;   // exclusive
    if (tid == 1023) d_bsum[blockIdx.x] = sh[1023];
}

__global__ void scan2_k() {
    if (threadIdx.x == 0) {
        int acc = 0;
        for (int b = 0; b < SCAN_NB; b++) { int t = d_bsum[b]; d_bsum[b] = acc; acc += t; }
    }
}

__global__ void scan3_k() {
    int i = blockIdx.x * blockDim.x + threadIdx.x;
    if (i < NN) {
        int r = d_rowptr[i] + d_bsum[i >> 10];
        d_rowptr[i] = r;
        d_cursor[i] = r;
        d_dinv[i] = rsqrtf((float)(d_deg[i] + 1));  // +1 self-loop
    }
    if (i == 0) d_rowptr[NN] = NE;
}

__global__ void scatter_k(const int* __restrict__ ei) {
    int e = blockIdx.x * blockDim.x + threadIdx.x;
    if (e >= NE) return;
    int s = ei[e];
    int t = ei[NE + e];
    int p = atomicAdd(&d_cursor[t], 1);
    d_col[p] = s;
    d_w[p] = d_dinv[s] * d_dinv[t];
}

// ---------------- h0 = x @ Wp + bp ----------------
__global__ void h0_k(const float* __restrict__ x, const float* __restrict__ Wp,
                     const float* __restrict__ bp) {
    int idx = blockIdx.x * blockDim.x + threadIdx.x;
    if (idx >= NN * HID) return;
    int v = idx >> 7, c = idx & 127;
    float s = bp[c];
#pragma unroll
    for (int k = 0; k < INDIM; k++) s = fmaf(x[v * INDIM + k], Wp[k * HID + c], s);
    d_bufH[idx] = s;
}

// ---------------- fused (BN+ReLU) + GEMM:  M = act(A) @ W ----------------
__global__ void __launch_bounds__(256) gemm_k(const float* __restrict__ W, int srcA, int useBN) {
    extern __shared__ float sm[];
    float* Ws = sm;               // 128 x 128
    float* As = sm + 128 * 128;   // 64 x 132 (padded)
    const float* A = srcA ? d_bufA : d_bufH;
    int tid = threadIdx.x;
    int row0 = blockIdx.x * 64;

    for (int i = tid; i < 4096; i += 256) ((float4*)Ws)[i] = ((const float4*)W)[i];
    for (int i = tid; i < 2048; i += 256) {
        int r = i >> 5;
        int c = (i & 31) << 2;
        float4 v = *(const float4*)(A + (size_t)(row0 + r) * HID + c);
        if (useBN) {
            v.x = fmaxf(fmaf(d_bnA[c    ], v.x, d_bnB[c    ]), 0.f);
            v.y = fmaxf(fmaf(d_bnA[c + 1], v.y, d_bnB[c + 1]), 0.f);
            v.z = fmaxf(fmaf(d_bnA[c + 2], v.z, d_bnB[c + 2]), 0.f);
            v.w = fmaxf(fmaf(d_bnA[c + 3], v.w, d_bnB[c + 3]), 0.f);
        }
        *(float4*)(As + r * 132 + c) = v;
    }
    __syncthreads();

    int tx = tid & 15, ty = tid >> 4;
    unsigned long long acc[4][4];
#pragma unroll
    for (int r = 0; r < 4; r++)
#pragma unroll
        for (int j = 0; j < 4; j++) acc[r][j] = 0ull;

    const float* Asr = As + (ty * 4) * 132;
#pragma unroll 4
    for (int k = 0; k < 128; k++) {
        unsigned long long w2[4];
#pragma unroll
        for (int j = 0; j < 4; j++)
            w2[j] = *(const unsigned long long*)(Ws + k * 128 + j * 32 + tx * 2);
#pragma unroll
        for (int r = 0; r < 4; r++) {
            float a = Asr[r * 132 + k];
            unsigned long long a2 = pack2(a, a);
#pragma unroll
            for (int j = 0; j < 4; j++) fma2(acc[r][j], a2, w2[j]);
        }
    }

#pragma unroll
    for (int r = 0; r < 4; r++) {
        size_t row = row0 + ty * 4 + r;
#pragma unroll
        for (int j = 0; j < 4; j++) {
            float2 v = unpack2(acc[r][j]);
            *(float2*)(d_bufM + row * HID + j * 32 + tx * 2) = v;
        }
    }
}

// ---------------- aggregation: agg = Ahat @ M + bg (warp per node, CSR) ----------------
__global__ void agg_k(const float* __restrict__ bg) {
    int w = (blockIdx.x * blockDim.x + threadIdx.x) >> 5;
    int lane = threadIdx.x & 31;
    if (w >= NN) return;
    int st = d_rowptr[w], en = d_rowptr[w + 1];
    float4 acc = make_float4(0.f, 0.f, 0.f, 0.f);
    for (int e = st; e < en; e++) {
        int s = __ldg(&d_col[e]);
        float wt = __ldg(&d_w[e]);
        float4 mv = *(const float4*)(d_bufM + (size_t)s * HID + lane * 4);
        acc.x = fmaf(wt, mv.x, acc.x);
        acc.y = fmaf(wt, mv.y, acc.y);
        acc.z = fmaf(wt, mv.z, acc.z);
        acc.w = fmaf(wt, mv.w, acc.w);
    }
    float di = d_dinv[w];
    float ws = di * di;
    float4 mv = *(const float4*)(d_bufM + (size_t)w * HID + lane * 4);
    float4 b = *(const float4*)(bg + lane * 4);
    acc.x = fmaf(ws, mv.x, acc.x) + b.x;
    acc.y = fmaf(ws, mv.y, acc.y) + b.y;
    acc.z = fmaf(ws, mv.z, acc.z) + b.z;
    acc.w = fmaf(ws, mv.w, acc.w) + b.w;
    *(float4*)(d_bufA + (size_t)w * HID + lane * 4) = acc;
}

// ---------------- BN statistics ----------------
__global__ void zero_sums_k() {
    if (threadIdx.x < 2 * HID) d_sums[threadIdx.x] = 0.f;
}

__global__ void stats_k() {
    __shared__ float sh_s[256], sh_q[256];
    int tid = threadIdx.x;
    int ch = tid & 127, half = tid >> 7;
    float s = 0.f, q = 0.f;
    for (int r = blockIdx.x * 2 + half; r < NN; r += gridDim.x * 2) {
        float v = d_bufA[(size_t)r * HID + ch];
        s += v;
        q += v * v;
    }
    sh_s[tid] = s;
    sh_q[tid] = q;
    __syncthreads();
    if (tid < 128) {
        atomicAdd(&d_sums[tid], sh_s[tid] + sh_s[tid + 128]);
        atomicAdd(&d_sums[128 + tid], sh_q[tid] + sh_q[tid + 128]);
    }
}

__global__ void finalize_k(const float* __restrict__ gamma, const float* __restrict__ beta) {
    int c = threadIdx.x;
    if (c >= HID) return;
    float mu = d_sums[c] * (1.0f / NN);
    float var = d_sums[128 + c] * (1.0f / NN) - mu * mu;
    float rstd = rsqrtf(var + 1e-5f);
    float a = gamma[c] * rstd;
    d_bnA[c] = a;
    d_bnB[c] = beta[c] - mu * a;
}

// ---------------- pooling ----------------
__global__ void gbounds_k(const int* __restrict__ batch) {
    int g = threadIdx.x;
    if (g > NG) return;
    int lo = 0, hi = NN;
    while (lo < hi) {
        int mid = (lo + hi) >> 1;
        if (batch[mid] < g) lo = mid + 1; else hi = mid;
    }
    d_gstart[g] = lo;
}

__global__ void pool_k() {
    __shared__ float sh_s[256], sh_m[256];
    int g = blockIdx.x;
    int st = d_gstart[g], en = d_gstart[g + 1];
    int tid = threadIdx.x;
    int ch = tid & 127, half = tid >> 7;
    float a = d_bnA[ch], b = d_bnB[ch];
    float s = 0.f, mx = 0.f;
    for (int r = st + half; r < en; r += 2) {
        float v = fmaxf(fmaf(a, d_bufA[(size_t)r * HID + ch], b), 0.f);
        s += v;
        mx = fmaxf(mx, v);
    }
    sh_s[tid] = s;
    sh_m[tid] = mx;
    __syncthreads();
    if (tid < 128) {
        float cnt = (float)(en - st);
        float tot = sh_s[tid] + sh_s[tid + 128];
        d_pooled[g * 256 + tid] = tot / fmaxf(cnt, 1.0f);
        d_pooled[g * 256 + 128 + tid] = fmaxf(sh_m[tid], sh_m[tid + 128]);
    }
}

// ---------------- MLP head ----------------
__global__ void mlp1_k(const float* __restrict__ W1, const float* __restrict__ b1) {
    __shared__ float sp[256];
    int g = blockIdx.x, j = threadIdx.x;
    sp[j] = d_pooled[g * 256 + j];
    sp[j + 128] = d_pooled[g * 256 + 128 + j];
    __syncthreads();
    float s = b1[j];
#pragma unroll 8
    for (int k = 0; k < 256; k++) s = fmaf(sp[k], W1[k * HID + j], s);
    d_h1[g * HID + j] = fmaxf(s, 0.f);
}

__global__ void mlp2_k(const float* __restrict__ W2, const float* __restrict__ b2) {
    __shared__ float sh[128];
    int g = blockIdx.x, j = threadIdx.x;
    sh[j] = d_h1[g * HID + j];
    sh[j + 64] = d_h1[g * HID + j + 64];
    __syncthreads();
    float s = b2[j];
#pragma unroll 8
    for (int k = 0; k < 128; k++) s = fmaf(sh[k], W2[k * 64 + j], s);
    d_h2[g * 64 + j] = fmaxf(s, 0.f);
}

__global__ void mlp3_k(const float* __restrict__ W3, const float* __restrict__ b3,
                       float* __restrict__ out) {
    int tid = threadIdx.x;
    if (tid >= NG * NCLS) return;
    int g = tid / NCLS, c = tid % NCLS;
    float s = b3[c];
#pragma unroll 8
    for (int k = 0; k < 64; k++) s = fmaf(d_h2[g * 64 + k], W3[k * NCLS + c], s);
    out[tid] = s;
}

// ---------------- launch ----------------
extern "C" void kernel_launch(void* const* d_in, const int* in_sizes, int n_in,
                              void* d_out, int out_size) {
    const float* x     = (const float*)d_in[0];
    const int*   ei    = (const int*)d_in[1];
    const int*   batch = (const int*)d_in[2];
    const float* Wp    = (const float*)d_in[3];
    const float* bp    = (const float*)d_in[4];
    const float* Wg    = (const float*)d_in[5];
    const float* bg    = (const float*)d_in[6];
    const float* gamma = (const float*)d_in[7];
    const float* beta  = (const float*)d_in[8];
    const float* W1    = (const float*)d_in[9];
    const float* b1    = (const float*)d_in[10];
    const float* W2    = (const float*)d_in[11];
    const float* b2    = (const float*)d_in[12];
    const float* W3    = (const float*)d_in[13];
    const float* b3    = (const float*)d_in[14];
    float* out = (float*)d_out;

    cudaFuncSetAttribute(gemm_k, cudaFuncAttributeMaxDynamicSharedMemorySize, GEMM_SMEM);

    // CSR build (per-launch, deterministic work)
    zero_deg_k<<<(NN + 255) / 256, 256>>>();
    hist_k<<<(NE + 255) / 256, 256>>>(ei);
    scan1_k<<<SCAN_NB, 1024>>>();
    scan2_k<<<1, 32>>>();
    scan3_k<<<(NN + 255) / 256, 256>>>();
    scatter_k<<<(NE + 255) / 256, 256>>>(ei);

    // input projection
    h0_k<<<(NN * HID + 255) / 256, 256>>>(x, Wp, bp);
    gbounds_k<<<1, 128>>>(batch);

    for (int i = 0; i < NL; i++) {
        gemm_k<<<NP / 64, 256, GEMM_SMEM>>>(Wg + (size_t)i * HID * HID, i > 0 ? 1 : 0, i > 0 ? 1 : 0);
        agg_k<<<(NN + 7) / 8, 256>>>(bg + i * HID);
        zero_sums_k<<<1, 256>>>();
        stats_k<<<256, 256>>>();
        finalize_k<<<1, 128>>>(gamma + i * HID, beta + i * HID);
    }

    pool_k<<<NG, 256>>>();
    mlp1_k<<<NG, 128>>>(W1, b1);
    mlp2_k<<<NG, 64>>>(W2, b2);
    mlp3_k<<<1, 512>>>(W3, b3, out);
}

// round 6
// speedup vs baseline: 1.2488x; 1.2488x over previous
#include <cuda_runtime.h>
#include <cstdint>

#define NN 50000
#define NP 50048
#define NE 600000
#define NG 64
#define HID 128
#define NL 4
#define INDIM 5
#define NCLS 5
#define SCAN_NB 49

// ---------------- device scratch ----------------
__device__ int   d_deg[NN];
__device__ int   d_rowptr[NN + 1];
__device__ int   d_cursor[NN];
__device__ int2  d_colw[NE];                 // packed (src, weight-bits)
__device__ float d_dinv[NN];
__device__ int   d_bsum[64];
__device__ float d_bufM[(size_t)NP * HID];
__device__ float d_bufA[(size_t)NP * HID];
__device__ float d_sums[2][256];             // [parity][0..127 sum, 128..255 sumsq]
__device__ int   d_gstart[NG + 1];

// ---------------- f32x2 packed-fp32 helpers (sm_103 core ISA) ----------------
__device__ __forceinline__ unsigned long long pack2(float x, float y) {
    unsigned long long r;
    asm("mov.b64 %0, {%1, %2};" : "=l"(r) : "f"(x), "f"(y));
    return r;
}
__device__ __forceinline__ void fma2(unsigned long long &d, unsigned long long a, unsigned long long b) {
    asm("fma.rn.f32x2 %0, %1, %2, %0;" : "+l"(d) : "l"(a), "l"(b));
}
__device__ __forceinline__ float2 unpack2(unsigned long long v) {
    float2 r;
    asm("mov.b64 {%0, %1}, %2;" : "=f"(r.x), "=f"(r.y) : "l"(v));
    return r;
}

// ---------------- wprep: gbounds + zero deg + zero sums ----------------
__global__ void wprep_k(const int* __restrict__ batch) {
    int b = blockIdx.x, tid = threadIdx.x;
    if (b == 0) {
        if (tid <= NG) {
            int g = tid, lo = 0, hi = NN;
            while (lo < hi) { int mid = (lo + hi) >> 1; if (batch[mid] < g) lo = mid + 1; else hi = mid; }
            d_gstart[g] = lo;
        }
        if (tid < 256) { d_sums[0][tid] = 0.f; d_sums[1][tid] = 0.f; }
    } else {
        for (int i = (b - 1) * 256 + tid; i < NN; i += (gridDim.x - 1) * 256) d_deg[i] = 0;
    }
}

// ---------------- CSR build ----------------
__global__ void hist_k(const int* __restrict__ ei) {
    int e = blockIdx.x * blockDim.x + threadIdx.x;
    if (e < NE) atomicAdd(&d_deg[ei[NE + e]], 1);
}

__global__ void scan1_k() {
    __shared__ int sh[1024];
    int tid = threadIdx.x;
    int i = blockIdx.x * 1024 + tid;
    int v = (i < NN) ? d_deg[i] : 0;
    sh[tid] = v;
    __syncthreads();
    for (int off = 1; off < 1024; off <<= 1) {
        int t = (tid >= off) ? sh[tid - off] : 0;
        __syncthreads();
        sh[tid] += t;
        __syncthreads();
    }
    if (i < NN) d_rowptr[i] = sh[tid] - v;
    if (tid == 1023) d_bsum[blockIdx.x] = sh[1023];
}

__global__ void scan3_k() {
    __shared__ int pref;
    int tid = threadIdx.x;
    if (tid == 0) {
        int acc = 0;
        for (int b = 0; b < blockIdx.x; b++) acc += d_bsum[b];
        pref = acc;
    }
    __syncthreads();
    int i = blockIdx.x * 1024 + tid;
    if (i < NN) {
        int r = d_rowptr[i] + pref;
        d_rowptr[i] = r;
        d_cursor[i] = r;
        d_dinv[i] = rsqrtf((float)(d_deg[i] + 1));
    }
    if (i == 0) d_rowptr[NN] = NE;
}

__global__ void scatter_k(const int* __restrict__ ei) {
    int e = blockIdx.x * blockDim.x + threadIdx.x;
    if (e >= NE) return;
    int s = ei[e], t = ei[NE + e];
    int p = atomicAdd(&d_cursor[t], 1);
    int2 v;
    v.x = s;
    v.y = __float_as_int(d_dinv[s] * d_dinv[t]);
    d_colw[p] = v;
}

// ---------------- fused GEMM: M = act(A) @ W (SIMT f32x2) ----------------
// smem: Ws 128x128 (65536 B) | As 64x132 (33792 B) | extra 768 f (3072 B)
#define GEMM_SMEM ((128 * 128 + 64 * 132 + 768) * 4)

__global__ void __launch_bounds__(256, 1) gemm_k(
    const float* __restrict__ W, const float* __restrict__ x,
    const float* __restrict__ Wp, const float* __restrict__ bp,
    const float* __restrict__ gammaP, const float* __restrict__ betaP, int layer)
{
    extern __shared__ float sm[];
    float* Ws = sm;                       // 128 x 128
    float* As = sm + 128 * 128;           // 64 x 132
    float* sx = As + 64 * 132;            // 768: layer0 = Wp+bp, layer>0 = BN coefs
    int tid = threadIdx.x;
    int row0 = blockIdx.x * 64;

    // zero next layer's stats buffer (block 0 only; runs before this layer's agg)
    if (blockIdx.x == 0) d_sums[layer & 1][tid & 255] = 0.f;

    if (layer == 0) {
        for (int i = tid; i < INDIM * HID; i += 256) sx[i] = Wp[i];
        if (tid < HID) sx[INDIM * HID + tid] = bp[tid];
    } else if (tid < HID) {
        int par = (layer - 1) & 1;
        float mu = d_sums[par][tid] * (1.0f / NN);
        float var = d_sums[par][128 + tid] * (1.0f / NN) - mu * mu;
        float a = gammaP[tid] * rsqrtf(var + 1e-5f);
        sx[tid] = a;
        sx[128 + tid] = betaP[tid] - mu * a;
    }

    for (int i = tid; i < 4096; i += 256) ((float4*)Ws)[i] = ((const float4*)W)[i];
    __syncthreads();   // sx ready before A-tile build

    for (int i = tid; i < 2048; i += 256) {
        int r = i >> 5;
        int c = (i & 31) << 2;
        float4 v;
        if (layer == 0) {
            int gr = row0 + r;
            float xr[INDIM];
#pragma unroll
            for (int j = 0; j < INDIM; j++) xr[j] = (gr < NN) ? __ldg(&x[gr * INDIM + j]) : 0.f;
            float o[4];
#pragma unroll
            for (int cc = 0; cc < 4; cc++) {
                float s = sx[INDIM * HID + c + cc];
#pragma unroll
                for (int j = 0; j < INDIM; j++) s = fmaf(xr[j], sx[j * HID + c + cc], s);
                o[cc] = s;
            }
            v = make_float4(o[0], o[1], o[2], o[3]);
        } else {
            v = *(const float4*)(d_bufA + (size_t)(row0 + r) * HID + c);
            v.x = fmaxf(fmaf(sx[c    ], v.x, sx[128 + c    ]), 0.f);
            v.y = fmaxf(fmaf(sx[c + 1], v.y, sx[128 + c + 1]), 0.f);
            v.z = fmaxf(fmaf(sx[c + 2], v.z, sx[128 + c + 2]), 0.f);
            v.w = fmaxf(fmaf(sx[c + 3], v.w, sx[128 + c + 3]), 0.f);
        }
        *(float4*)(As + r * 132 + c) = v;
    }
    __syncthreads();

    int tx = tid & 15, ty = tid >> 4;
    unsigned long long acc[4][4];
#pragma unroll
    for (int r = 0; r < 4; r++)
#pragma unroll
        for (int j = 0; j < 4; j++) acc[r][j] = 0ull;

    const float* Asr = As + (ty * 4) * 132;
#pragma unroll 4
    for (int k = 0; k < 128; k++) {
        unsigned long long w2[4];
#pragma unroll
        for (int j = 0; j < 4; j++)
            w2[j] = *(const unsigned long long*)(Ws + k * 128 + j * 32 + tx * 2);
#pragma unroll
        for (int r = 0; r < 4; r++) {
            float a = Asr[r * 132 + k];
            unsigned long long a2 = pack2(a, a);
#pragma unroll
            for (int j = 0; j < 4; j++) fma2(acc[r][j], a2, w2[j]);
        }
    }

#pragma unroll
    for (int r = 0; r < 4; r++) {
        size_t row = row0 + ty * 4 + r;
#pragma unroll
        for (int j = 0; j < 4; j++) {
            float2 v = unpack2(acc[r][j]);
            *(float2*)(d_bufM + row * HID + j * 32 + tx * 2) = v;
        }
    }
}

// ---------------- aggregation + fused BN stats ----------------
__global__ void __launch_bounds__(256) agg_k(const float* __restrict__ bg, int par) {
    __shared__ float shs[128], shq[128];
    int tid = threadIdx.x;
    int lane = tid & 31;
    if (tid < 128) { shs[tid] = 0.f; shq[tid] = 0.f; }
    __syncthreads();

    float4 s4 = make_float4(0.f, 0.f, 0.f, 0.f);
    float4 q4 = make_float4(0.f, 0.f, 0.f, 0.f);
    float4 b = *reinterpret_cast<const float4*>(bg + lane * 4);

    int w0 = blockIdx.x * 8 + (tid >> 5);
    int stride = gridDim.x * 8;
    for (int n = w0; n < NN; n += stride) {
        int st = d_rowptr[n], en = d_rowptr[n + 1];
        float4 acc = make_float4(0.f, 0.f, 0.f, 0.f);
        for (int e = st; e < en; e++) {
            int2 cw = __ldg(&d_colw[e]);
            float wt = __int_as_float(cw.y);
            float4 mv = *reinterpret_cast<const float4*>(d_bufM + (size_t)cw.x * HID + lane * 4);
            acc.x = fmaf(wt, mv.x, acc.x);
            acc.y = fmaf(wt, mv.y, acc.y);
            acc.z = fmaf(wt, mv.z, acc.z);
            acc.w = fmaf(wt, mv.w, acc.w);
        }
        float di = d_dinv[n];
        float ws = di * di;
        float4 mv = *reinterpret_cast<const float4*>(d_bufM + (size_t)n * HID + lane * 4);
        acc.x = fmaf(ws, mv.x, acc.x) + b.x;
        acc.y = fmaf(ws, mv.y, acc.y) + b.y;
        acc.z = fmaf(ws, mv.z, acc.z) + b.z;
        acc.w = fmaf(ws, mv.w, acc.w) + b.w;
        *reinterpret_cast<float4*>(d_bufA + (size_t)n * HID + lane * 4) = acc;
        s4.x += acc.x; s4.y += acc.y; s4.z += acc.z; s4.w += acc.w;
        q4.x = fmaf(acc.x, acc.x, q4.x); q4.y = fmaf(acc.y, acc.y, q4.y);
        q4.z = fmaf(acc.z, acc.z, q4.z); q4.w = fmaf(acc.w, acc.w, q4.w);
    }

    int ch = lane * 4;
    atomicAdd(&shs[ch    ], s4.x); atomicAdd(&shs[ch + 1], s4.y);
    atomicAdd(&shs[ch + 2], s4.z); atomicAdd(&shs[ch + 3], s4.w);
    atomicAdd(&shq[ch    ], q4.x); atomicAdd(&shq[ch + 1], q4.y);
    atomicAdd(&shq[ch + 2], q4.z); atomicAdd(&shq[ch + 3], q4.w);
    __syncthreads();
    if (tid < 128) {
        atomicAdd(&d_sums[par][tid], shs[tid]);
        atomicAdd(&d_sums[par][128 + tid], shq[tid]);
    }
}

// ---------------- pool + MLP head (one kernel) ----------------
__global__ void __launch_bounds__(256) poolhead_k(
    const float* __restrict__ gamma3, const float* __restrict__ beta3,
    const float* __restrict__ W1, const float* __restrict__ b1,
    const float* __restrict__ W2, const float* __restrict__ b2,
    const float* __restrict__ W3, const float* __restrict__ b3,
    float* __restrict__ out)
{
    __shared__ float sbn[256], shs[256], shm[256], pooled[256], h1[128], h2[64];
    int g = blockIdx.x, tid = threadIdx.x;
    if (tid < 128) {
        float mu = d_sums[1][tid] * (1.0f / NN);
        float var = d_sums[1][128 + tid] * (1.0f / NN) - mu * mu;
        float a = gamma3[tid] * rsqrtf(var + 1e-5f);
        sbn[tid] = a;
        sbn[128 + tid] = beta3[tid] - mu * a;
    }
    __syncthreads();
    int st = d_gstart[g], en = d_gstart[g + 1];
    int ch = tid & 127, half = tid >> 7;
    float a = sbn[ch], bb = sbn[128 + ch];
    float s = 0.f, mx = 0.f;
    for (int r = st + half; r < en; r += 2) {
        float v = fmaxf(fmaf(a, d_bufA[(size_t)r * HID + ch], bb), 0.f);
        s += v;
        mx = fmaxf(mx, v);
    }
    shs[tid] = s;
    shm[tid] = mx;
    __syncthreads();
    if (tid < 128) {
        float cnt = (float)(en - st);
        pooled[tid] = (shs[tid] + shs[tid + 128]) / fmaxf(cnt, 1.0f);
        pooled[128 + tid] = fmaxf(shm[tid], shm[tid + 128]);
    }
    __syncthreads();
    if (tid < 128) {
        float acc = b1[tid];
#pragma unroll 8
        for (int k = 0; k < 256; k++) acc = fmaf(pooled[k], W1[k * HID + tid], acc);
        h1[tid] = fmaxf(acc, 0.f);
    }
    __syncthreads();
    if (tid < 64) {
        float acc = b2[tid];
#pragma unroll 8
        for (int k = 0; k < 128; k++) acc = fmaf(h1[k], W2[k * 64 + tid], acc);
        h2[tid] = fmaxf(acc, 0.f);
    }
    __syncthreads();
    if (tid < NCLS) {
        float acc = b3[tid];
#pragma unroll 8
        for (int k = 0; k < 64; k++) acc = fmaf(h2[k], W3[k * NCLS + tid], acc);
        out[g * NCLS + tid] = acc;
    }
}

// ---------------- launch ----------------
extern "C" void kernel_launch(void* const* d_in, const int* in_sizes, int n_in,
                              void* d_out, int out_size) {
    const float* x     = (const float*)d_in[0];
    const int*   ei    = (const int*)d_in[1];
    const int*   batch = (const int*)d_in[2];
    const float* Wp    = (const float*)d_in[3];
    const float* bp    = (const float*)d_in[4];
    const float* Wg    = (const float*)d_in[5];
    const float* bg    = (const float*)d_in[6];
    const float* gamma = (const float*)d_in[7];
    const float* beta  = (const float*)d_in[8];
    const float* W1    = (const float*)d_in[9];
    const float* b1    = (const float*)d_in[10];
    const float* W2    = (const float*)d_in[11];
    const float* b2    = (const float*)d_in[12];
    const float* W3    = (const float*)d_in[13];
    const float* b3    = (const float*)d_in[14];
    float* out = (float*)d_out;

    cudaFuncSetAttribute(gemm_k, cudaFuncAttributeMaxDynamicSharedMemorySize, GEMM_SMEM);

    wprep_k<<<33, 256>>>(batch);
    hist_k<<<(NE + 255) / 256, 256>>>(ei);
    scan1_k<<<SCAN_NB, 1024>>>();
    scan3_k<<<SCAN_NB, 1024>>>();
    scatter_k<<<(NE + 255) / 256, 256>>>(ei);

    for (int i = 0; i < NL; i++) {
        gemm_k<<<NP / 64, 256, GEMM_SMEM>>>(
            Wg + (size_t)i * HID * HID, x, Wp, bp,
            i > 0 ? gamma + (i - 1) * HID : gamma,
            i > 0 ? beta + (i - 1) * HID : beta, i);
        agg_k<<<1024, 256>>>(bg + i * HID, i & 1);
    }

    poolhead_k<<<NG, 256>>>(gamma + 3 * HID, beta + 3 * HID, W1, b1, W2, b2, W3, b3, out);
}